// round 12
// baseline (speedup 1.0000x reference)
#include <cuda_runtime.h>

#define DIMN 32
#define TPB 256

__global__ __launch_bounds__(TPB, 3) void poly_scalar_persist3_kernel(
    const float* __restrict__ x,
    const float* __restrict__ w,
    float* __restrict__ out,
    int n_vec4)
{
    const float4* __restrict__ x4 = reinterpret_cast<const float4*>(x);
    float4* __restrict__ o4 = reinterpret_cast<float4*>(out);
    const int tid = threadIdx.x;

    // ---- all 32 coefficients in scalar registers, loaded once ----
    // (launch_bounds(256,3) gives an 85-reg budget: no spill this time)
#define LDW(i) float w##i = __ldg(&w[i]);
    LDW(0)  LDW(1)  LDW(2)  LDW(3)  LDW(4)  LDW(5)  LDW(6)  LDW(7)
    LDW(8)  LDW(9)  LDW(10) LDW(11) LDW(12) LDW(13) LDW(14) LDW(15)
    LDW(16) LDW(17) LDW(18) LDW(19) LDW(20) LDW(21) LDW(22) LDW(23)
    LDW(24) LDW(25) LDW(26) LDW(27) LDW(28) LDW(29) LDW(30) LDW(31)
#undef LDW

    const int stride = gridDim.x * (2 * TPB);   // float4s per sweep
    int i = blockIdx.x * (2 * TPB) + tid;

    // ---- prologue: first pair of float4s ----
    float4 curA = (i < n_vec4) ? __ldg(&x4[i])
                               : make_float4(0.f, 0.f, 0.f, 0.f);
    float4 curB = (i + TPB < n_vec4) ? __ldg(&x4[i + TPB])
                                     : make_float4(0.f, 0.f, 0.f, 0.f);

    while (i < n_vec4) {
        // ---- prefetch next sweep before the compute burst ----
        int ni = i + stride;
        float4 nxtA = (ni < n_vec4) ? __ldg(&x4[ni])
                                    : make_float4(0.f, 0.f, 0.f, 0.f);
        float4 nxtB = (ni + TPB < n_vec4) ? __ldg(&x4[ni + TPB])
                                          : make_float4(0.f, 0.f, 0.f, 0.f);

        // ---- 8 independent scalar Horner chains (named regs only) ----
        float p0 = curA.x, p1 = curA.y, p2 = curA.z, p3 = curA.w;
        float p4 = curB.x, p5 = curB.y, p6 = curB.z, p7 = curB.w;

        float a0 = w31, a1 = w31, a2 = w31, a3 = w31;
        float a4 = w31, a5 = w31, a6 = w31, a7 = w31;

#define STEP(WK) \
        a0 = fmaf(a0, p0, WK); a1 = fmaf(a1, p1, WK); \
        a2 = fmaf(a2, p2, WK); a3 = fmaf(a3, p3, WK); \
        a4 = fmaf(a4, p4, WK); a5 = fmaf(a5, p5, WK); \
        a6 = fmaf(a6, p6, WK); a7 = fmaf(a7, p7, WK);

        STEP(w30) STEP(w29) STEP(w28) STEP(w27) STEP(w26) STEP(w25)
        STEP(w24) STEP(w23) STEP(w22) STEP(w21) STEP(w20) STEP(w19)
        STEP(w18) STEP(w17) STEP(w16) STEP(w15) STEP(w14) STEP(w13)
        STEP(w12) STEP(w11) STEP(w10) STEP(w9)  STEP(w8)  STEP(w7)
        STEP(w6)  STEP(w5)  STEP(w4)  STEP(w3)  STEP(w2)  STEP(w1)
        STEP(w0)
#undef STEP

        if (i < n_vec4)
            o4[i] = make_float4(a0, a1, a2, a3);
        if (i + TPB < n_vec4)
            o4[i + TPB] = make_float4(a4, a5, a6, a7);

        curA = nxtA;
        curB = nxtB;
        i = ni;
    }
}

extern "C" void kernel_launch(void* const* d_in, const int* in_sizes, int n_in,
                              void* d_out, int out_size) {
    const float* x = (const float*)d_in[0];
    const float* w = (const float*)d_in[1];
    float* out = (float*)d_out;

    int n = in_sizes[0];            // 4194304
    int n_vec4 = n / 4;             // 1048576 float4s

    int sms = 148;
    cudaDeviceGetAttribute(&sms, cudaDevAttrMultiProcessorCount, 0);
    int blocks = sms * 3;           // exactly resident at 3 blocks/SM
    int max_blocks = (n_vec4 + 2 * TPB - 1) / (2 * TPB);
    if (blocks > max_blocks) blocks = max_blocks;

    poly_scalar_persist3_kernel<<<blocks, TPB>>>(x, w, out, n_vec4);
}

// round 13
// speedup vs baseline: 1.0255x; 1.0255x over previous
#include <cuda_runtime.h>

#define DIMN 32
#define TPB 256

__device__ __forceinline__ unsigned long long pack2(float lo, float hi) {
    unsigned long long r;
    asm("mov.b64 %0, {%1, %2};" : "=l"(r) : "f"(lo), "f"(hi));
    return r;
}
__device__ __forceinline__ void unpack2(unsigned long long v, float& lo, float& hi) {
    asm("mov.b64 {%0, %1}, %2;" : "=f"(lo), "=f"(hi) : "l"(v));
}
__device__ __forceinline__ unsigned long long fma2(unsigned long long a,
                                                   unsigned long long b,
                                                   unsigned long long c) {
    unsigned long long d;
    asm("fma.rn.f32x2 %0, %1, %2, %3;" : "=l"(d) : "l"(a), "l"(b), "l"(c));
    return d;
}

__global__ __launch_bounds__(TPB, 6) void poly_maxocc_kernel(
    const float* __restrict__ x,
    const float* __restrict__ w,
    float* __restrict__ out,
    int n_vec4)
{
    // Coefficients packed into smem once per block (fused; single launch).
    __shared__ unsigned long long s_wp[DIMN];
    if (threadIdx.x < DIMN) {
        float wk = __ldg(&w[threadIdx.x]);
        s_wp[threadIdx.x] = pack2(wk, wk);
    }
    __syncthreads();

    int i = blockIdx.x * TPB + threadIdx.x;
    if (i >= n_vec4) return;

    const float4* __restrict__ x4 = reinterpret_cast<const float4*>(x);
    float4* __restrict__ o4 = reinterpret_cast<float4*>(out);

    float4 xv = __ldg(&x4[i]);

    unsigned long long p0 = pack2(xv.x, xv.y);
    unsigned long long p1 = pack2(xv.z, xv.w);

    unsigned long long a0 = s_wp[DIMN - 1];
    unsigned long long a1 = a0;

    // 31 steps: one broadcast LDS.64 feeds 2 FFMA2. Minimal body, no arrays.
#pragma unroll
    for (int k = DIMN - 2; k >= 0; --k) {
        unsigned long long wk = s_wp[k];
        a0 = fma2(a0, p0, wk);
        a1 = fma2(a1, p1, wk);
    }

    float4 ov;
    unpack2(a0, ov.x, ov.y);
    unpack2(a1, ov.z, ov.w);
    o4[i] = ov;
}

extern "C" void kernel_launch(void* const* d_in, const int* in_sizes, int n_in,
                              void* d_out, int out_size) {
    const float* x = (const float*)d_in[0];
    const float* w = (const float*)d_in[1];
    float* out = (float*)d_out;

    int n = in_sizes[0];            // 4194304
    int n_vec4 = n / 4;             // 1048576 float4s
    int blocks = (n_vec4 + TPB - 1) / TPB;   // 4096

    poly_maxocc_kernel<<<blocks, TPB>>>(x, w, out, n_vec4);
}

// round 14
// speedup vs baseline: 1.0469x; 1.0208x over previous
#include <cuda_runtime.h>

#define DIMN 32
#define TPB 256

__constant__ float c_w[DIMN];

__global__ __launch_bounds__(TPB) void poly_cmem_kernel(
    const float* __restrict__ x,
    float* __restrict__ out,
    int n_vec4)
{
    int i = blockIdx.x * TPB + threadIdx.x;
    if (i >= n_vec4) return;

    const float4* __restrict__ x4 = reinterpret_cast<const float4*>(x);
    float4* __restrict__ o4 = reinterpret_cast<float4*>(out);

    float4 xv = __ldg(&x4[i]);

    float a0 = c_w[DIMN - 1];
    float a1 = a0, a2 = a0, a3 = a0;

    // 31 Horner steps, 4 independent scalar chains.
    // Coefficients come from the constant cache (uniform port),
    // NOT the L1tex pipe — one uniform load feeds all 4 FMAs.
#pragma unroll
    for (int k = DIMN - 2; k >= 0; --k) {
        float wk = c_w[k];
        a0 = fmaf(a0, xv.x, wk);
        a1 = fmaf(a1, xv.y, wk);
        a2 = fmaf(a2, xv.z, wk);
        a3 = fmaf(a3, xv.w, wk);
    }

    o4[i] = make_float4(a0, a1, a2, a3);
}

extern "C" void kernel_launch(void* const* d_in, const int* in_sizes, int n_in,
                              void* d_out, int out_size) {
    const float* x = (const float*)d_in[0];
    const float* w = (const float*)d_in[1];
    float* out = (float*)d_out;

    int n = in_sizes[0];            // 4194304
    int n_vec4 = n / 4;             // 1048576 float4s
    int blocks = (n_vec4 + TPB - 1) / TPB;   // 4096

    // Graph-capturable: async D2D copy into constant bank.
    cudaMemcpyToSymbolAsync(c_w, w, DIMN * sizeof(float), 0,
                            cudaMemcpyDeviceToDevice, 0);

    poly_cmem_kernel<<<blocks, TPB>>>(x, out, n_vec4);
}

// round 15
// speedup vs baseline: 1.2145x; 1.1601x over previous
#include <cuda_runtime.h>

#define DIMN 32
#define TPB 256

__constant__ float c_w[DIMN];

__device__ __forceinline__ unsigned long long pack2(float lo, float hi) {
    unsigned long long r;
    asm("mov.b64 %0, {%1, %2};" : "=l"(r) : "f"(lo), "f"(hi));
    return r;
}
__device__ __forceinline__ void unpack2(unsigned long long v, float& lo, float& hi) {
    asm("mov.b64 {%0, %1}, %2;" : "=f"(lo), "=f"(hi) : "l"(v));
}
__device__ __forceinline__ unsigned long long fma2(unsigned long long a,
                                                   unsigned long long b,
                                                   unsigned long long c) {
    unsigned long long d;
    asm("fma.rn.f32x2 %0, %1, %2, %3;" : "=l"(d) : "l"(a), "l"(b), "l"(c));
    return d;
}

__global__ __launch_bounds__(TPB, 5) void poly_cmem_f32x2_kernel(
    const float* __restrict__ x,
    float* __restrict__ out,
    int n_vec4)
{
    // Block owns 2*TPB consecutive float4s; thread takes 2 strided by TPB.
    int base = blockIdx.x * (2 * TPB) + threadIdx.x;
    int i0 = base;
    int i1 = base + TPB;

    const float4* __restrict__ x4 = reinterpret_cast<const float4*>(x);
    float4* __restrict__ o4 = reinterpret_cast<float4*>(out);

    float4 xv0 = (i0 < n_vec4) ? __ldg(&x4[i0]) : make_float4(0.f, 0.f, 0.f, 0.f);
    float4 xv1 = (i1 < n_vec4) ? __ldg(&x4[i1]) : make_float4(0.f, 0.f, 0.f, 0.f);

    // 4 independent packed chains = 8 elements (named u64 scalars only).
    unsigned long long p0 = pack2(xv0.x, xv0.y);
    unsigned long long p1 = pack2(xv0.z, xv0.w);
    unsigned long long p2 = pack2(xv1.x, xv1.y);
    unsigned long long p3 = pack2(xv1.z, xv1.w);

    float w31 = c_w[DIMN - 1];
    unsigned long long a0 = pack2(w31, w31);
    unsigned long long a1 = a0, a2 = a0, a3 = a0;

    // Per step: 1 LDC (constant bank, uniform port) + 1 mov.b64 + 4 FFMA2.
#pragma unroll
    for (int k = DIMN - 2; k >= 0; --k) {
        float wk = c_w[k];
        unsigned long long wkk = pack2(wk, wk);
        a0 = fma2(a0, p0, wkk);
        a1 = fma2(a1, p1, wkk);
        a2 = fma2(a2, p2, wkk);
        a3 = fma2(a3, p3, wkk);
    }

    float4 ov;
    if (i0 < n_vec4) {
        unpack2(a0, ov.x, ov.y);
        unpack2(a1, ov.z, ov.w);
        o4[i0] = ov;
    }
    if (i1 < n_vec4) {
        unpack2(a2, ov.x, ov.y);
        unpack2(a3, ov.z, ov.w);
        o4[i1] = ov;
    }
}

extern "C" void kernel_launch(void* const* d_in, const int* in_sizes, int n_in,
                              void* d_out, int out_size) {
    const float* x = (const float*)d_in[0];
    const float* w = (const float*)d_in[1];
    float* out = (float*)d_out;

    int n = in_sizes[0];            // 4194304
    int n_vec4 = n / 4;             // 1048576 float4s
    int blocks = (n_vec4 + 2 * TPB - 1) / (2 * TPB);   // 2048

    // Graph-capturable async D2D copy into the constant bank (proven in R14).
    cudaMemcpyToSymbolAsync(c_w, w, DIMN * sizeof(float), 0,
                            cudaMemcpyDeviceToDevice, 0);

    poly_cmem_f32x2_kernel<<<blocks, TPB>>>(x, out, n_vec4);
}

// round 16
// speedup vs baseline: 1.2563x; 1.0344x over previous
#include <cuda_runtime.h>

#define DIMN 32
#define TPB 256

__device__ __forceinline__ unsigned long long pack2(float lo, float hi) {
    unsigned long long r;
    asm("mov.b64 %0, {%1, %2};" : "=l"(r) : "f"(lo), "f"(hi));
    return r;
}
__device__ __forceinline__ void unpack2(unsigned long long v, float& lo, float& hi) {
    asm("mov.b64 {%0, %1}, %2;" : "=f"(lo), "=f"(hi) : "l"(v));
}
__device__ __forceinline__ unsigned long long fma2(unsigned long long a,
                                                   unsigned long long b,
                                                   unsigned long long c) {
    unsigned long long d;
    asm("fma.rn.f32x2 %0, %1, %2, %3;" : "=l"(d) : "l"(a), "l"(b), "l"(c));
    return d;
}

__global__ __launch_bounds__(TPB, 5) void poly_smem_f32x2_kernel(
    const float* __restrict__ x,
    const float* __restrict__ w,
    float* __restrict__ out,
    int n_vec4)
{
    // Fused coefficient packing: no memcpy node, no second launch.
    __shared__ unsigned long long s_wp[DIMN];
    if (threadIdx.x < DIMN) {
        float wk = __ldg(&w[threadIdx.x]);
        s_wp[threadIdx.x] = pack2(wk, wk);
    }
    __syncthreads();

    // Block owns 2*TPB consecutive float4s; thread takes 2 strided by TPB.
    int base = blockIdx.x * (2 * TPB) + threadIdx.x;
    int i0 = base;
    int i1 = base + TPB;

    const float4* __restrict__ x4 = reinterpret_cast<const float4*>(x);
    float4* __restrict__ o4 = reinterpret_cast<float4*>(out);

    float4 xv0 = (i0 < n_vec4) ? __ldg(&x4[i0]) : make_float4(0.f, 0.f, 0.f, 0.f);
    float4 xv1 = (i1 < n_vec4) ? __ldg(&x4[i1]) : make_float4(0.f, 0.f, 0.f, 0.f);

    // 4 independent packed chains = 8 elements (named u64 scalars only;
    // arrays would spill — R7; register-resident w would hoist/spill — R6/R12).
    unsigned long long p0 = pack2(xv0.x, xv0.y);
    unsigned long long p1 = pack2(xv0.z, xv0.w);
    unsigned long long p2 = pack2(xv1.x, xv1.y);
    unsigned long long p3 = pack2(xv1.z, xv1.w);

    unsigned long long a0 = s_wp[DIMN - 1];
    unsigned long long a1 = a0, a2 = a0, a3 = a0;

    // Per step: one broadcast LDS.64 feeds 4 FFMA2 (no LDC+mov pair needed).
#pragma unroll
    for (int k = DIMN - 2; k >= 0; --k) {
        unsigned long long wkk = s_wp[k];
        a0 = fma2(a0, p0, wkk);
        a1 = fma2(a1, p1, wkk);
        a2 = fma2(a2, p2, wkk);
        a3 = fma2(a3, p3, wkk);
    }

    float4 ov;
    if (i0 < n_vec4) {
        unpack2(a0, ov.x, ov.y);
        unpack2(a1, ov.z, ov.w);
        o4[i0] = ov;
    }
    if (i1 < n_vec4) {
        unpack2(a2, ov.x, ov.y);
        unpack2(a3, ov.z, ov.w);
        o4[i1] = ov;
    }
}

extern "C" void kernel_launch(void* const* d_in, const int* in_sizes, int n_in,
                              void* d_out, int out_size) {
    const float* x = (const float*)d_in[0];
    const float* w = (const float*)d_in[1];
    float* out = (float*)d_out;

    int n = in_sizes[0];            // 4194304
    int n_vec4 = n / 4;             // 1048576 float4s
    int blocks = (n_vec4 + 2 * TPB - 1) / (2 * TPB);   // 2048

    // ONE kernel launch, ONE graph node.
    poly_smem_f32x2_kernel<<<blocks, TPB>>>(x, w, out, n_vec4);
}